// round 2
// baseline (speedup 1.0000x reference)
#include <cuda_runtime.h>
#include <math.h>

#define NN 4
#define LL 4096
#define HH 16
#define DD 64
#define MM 64
#define CC 128
#define GG 32          // LL / CC
#define EPSF 1e-6f

typedef unsigned long long u64;

// Scratch (allocation-free per harness rules)
static __device__ float g_kv[(size_t)NN * GG * HH * DD * MM];   // 33.5 MB
static __device__ float g_ksum[(size_t)NN * GG * HH * DD];

__device__ __forceinline__ float phi(float x) {
    return x > 0.f ? x + 1.f : __expf(x);
}

// ---- packed f32x2 helpers (FFMA2: 2 FMAs per issue, ptxas won't emit it) ----
__device__ __forceinline__ u64 pk2(float lo, float hi) {
    u64 r; asm("mov.b64 %0,{%1,%2};" : "=l"(r) : "f"(lo), "f"(hi)); return r;
}
__device__ __forceinline__ u64 pkd(float v) {
    u64 r; asm("mov.b64 %0,{%1,%1};" : "=l"(r) : "f"(v)); return r;
}
__device__ __forceinline__ float2 up2(u64 v) {
    float2 f; asm("mov.b64 {%0,%1},%2;" : "=f"(f.x), "=f"(f.y) : "l"(v)); return f;
}
__device__ __forceinline__ void fma2(u64& d, u64 a, u64 b) {
    asm("fma.rn.f32x2 %0,%1,%2,%0;" : "+l"(d) : "l"(a), "l"(b));
}

// ---------------------------------------------------------------------------
// Kernel A: per-chunk KV state kv[d][m] = sum_c phi(k)[c][d] * v[c][m]
//           and ksum[d] = sum_c phi(k)[c][d]
// grid = N*G*H (2048), block = 256, dyn smem = 2*128*68*4 = 69632 B
// ---------------------------------------------------------------------------
__global__ void __launch_bounds__(256) chunk_state_kernel(
    const float* __restrict__ k, const float* __restrict__ v)
{
    extern __shared__ float sm[];
    float* sk = sm;              // [CC][68]
    float* sv = sm + CC * 68;    // [CC][68]

    int bid = blockIdx.x;
    int h = bid % HH;
    int g = (bid / HH) % GG;
    int n = bid / (HH * GG);
    size_t base = (((size_t)n * LL + (size_t)g * CC) * HH + h) * DD;
    int tid = threadIdx.x;

    for (int i = tid; i < CC * (DD / 4); i += 256) {
        int c = i >> 4;
        int dv = (i & 15) << 2;
        size_t off = base + (size_t)c * HH * DD + dv;
        float4 k4 = *(const float4*)(k + off);
        float4 v4 = *(const float4*)(v + off);
        float* pk_ = &sk[c * 68 + dv];
        pk_[0] = phi(k4.x); pk_[1] = phi(k4.y);
        pk_[2] = phi(k4.z); pk_[3] = phi(k4.w);
        *(float4*)&sv[c * 68 + dv] = v4;
    }
    __syncthreads();

    int ty = tid >> 4, tx = tid & 15;
    int d0 = ty * 4, m0 = tx * 4;
    u64 accp[4][2] = {};
#pragma unroll 4
    for (int c = 0; c < CC; c++) {
        float4 a4 = *(float4*)&sk[c * 68 + d0];
        float4 b4 = *(float4*)&sv[c * 68 + m0];
        u64 b0 = pk2(b4.x, b4.y), b1 = pk2(b4.z, b4.w);
        u64 a;
        a = pkd(a4.x); fma2(accp[0][0], a, b0); fma2(accp[0][1], a, b1);
        a = pkd(a4.y); fma2(accp[1][0], a, b0); fma2(accp[1][1], a, b1);
        a = pkd(a4.z); fma2(accp[2][0], a, b0); fma2(accp[2][1], a, b1);
        a = pkd(a4.w); fma2(accp[3][0], a, b0); fma2(accp[3][1], a, b1);
    }

    float* kvout = g_kv + (size_t)bid * DD * MM;
#pragma unroll
    for (int i = 0; i < 4; i++) {
        float2 lo = up2(accp[i][0]), hi = up2(accp[i][1]);
        *(float4*)(kvout + (size_t)(d0 + i) * MM + m0) =
            make_float4(lo.x, lo.y, hi.x, hi.y);
    }

    if (tid < DD) {
        float s = 0.f;
#pragma unroll 4
        for (int c = 0; c < CC; c++) s += sk[c * 68 + tid];
        g_ksum[(size_t)bid * DD + tid] = s;
    }
}

// ---------------------------------------------------------------------------
// Kernel B: exclusive prefix over chunks (axis g), in place.
// ---------------------------------------------------------------------------
__global__ void __launch_bounds__(256) prefix_kernel()
{
    int nh = blockIdx.x;
    int n = nh / HH, h = nh % HH;
    for (int pos = threadIdx.x; pos < DD * MM; pos += 256) {
        float run = 0.f;
        for (int g = 0; g < GG; g++) {
            size_t idx = (((size_t)(n * GG + g) * HH) + h) * (DD * MM) + pos;
            float t = g_kv[idx];
            g_kv[idx] = run;
            run += t;
        }
    }
    if (threadIdx.x < DD) {
        float run = 0.f;
        for (int g = 0; g < GG; g++) {
            size_t idx = (((size_t)(n * GG + g) * HH) + h) * DD + threadIdx.x;
            float t = g_ksum[idx];
            g_ksum[idx] = run;
            run += t;
        }
    }
}

// ---------------------------------------------------------------------------
// Kernel C: scores = tril(phi(q)phi(k)^T); z; out = (scores@v + q@kv_prev)/z
// grid = N*G*H (2048), block = 256, dyn smem = 190208 B
// ---------------------------------------------------------------------------
__global__ void __launch_bounds__(256) output_kernel(
    const float* __restrict__ q, const float* __restrict__ k,
    const float* __restrict__ v, float* __restrict__ out)
{
    extern __shared__ float sm[];
    float* sq  = sm;                 // [128][68]
    float* sk  = sq  + CC * 68;      // [128][68]
    float* sv  = sk  + CC * 68;      // [128][68]
    float* skv = sv  + CC * 68;      // [64][68]
    float* sks = skv + DD * 68;      // [64]
    float* sz  = sks + DD;           // [128]
    float* ss  = sz  + CC;           // [128][132]

    int bid = blockIdx.x;
    int h = bid % HH;
    int g = (bid / HH) % GG;
    int n = bid / (HH * GG);
    size_t base = (((size_t)n * LL + (size_t)g * CC) * HH + h) * DD;
    int tid = threadIdx.x;

    for (int i = tid; i < CC * (DD / 4); i += 256) {
        int c = i >> 4;
        int dv = (i & 15) << 2;
        size_t off = base + (size_t)c * HH * DD + dv;
        float4 q4 = *(const float4*)(q + off);
        float4 k4 = *(const float4*)(k + off);
        float4 v4 = *(const float4*)(v + off);
        float* pq_ = &sq[c * 68 + dv];
        float* pk_ = &sk[c * 68 + dv];
        pq_[0] = phi(q4.x); pq_[1] = phi(q4.y);
        pq_[2] = phi(q4.z); pq_[3] = phi(q4.w);
        pk_[0] = phi(k4.x); pk_[1] = phi(k4.y);
        pk_[2] = phi(k4.z); pk_[3] = phi(k4.w);
        *(float4*)&sv[c * 68 + dv] = v4;
    }
    {
        const float* kvp = g_kv + (size_t)bid * DD * MM;
        for (int i = tid; i < (DD * MM) / 4; i += 256) {
            int d = i >> 4;
            int mv = (i & 15) << 2;
            *(float4*)&skv[d * 68 + mv] = *(const float4*)(kvp + (size_t)d * MM + mv);
        }
        if (tid < DD) sks[tid] = g_ksum[(size_t)bid * DD + tid];
    }
    __syncthreads();

    int lane = tid & 31, w = tid >> 5;
    int wy = w >> 1, wx = w & 1;
    int ly = lane >> 3, lx = lane & 7;
    int r0 = (wy * 4 + ly) * 8;        // 8 output rows per thread
    int cg = wx * 8 + lx;              // 0..15
    int c0 = cg * 8;                   // scores: 8 cols per thread
    int m0 = cg * 4;                   // output: 4 cols per thread

    // ---- Phase 1: masked scores (packed f32x2) ----
    u64 accp[8][4] = {};               // [row][col-pair]
    if (c0 <= r0 + 7) {
        for (int d = 0; d < DD; d += 4) {
            float af[8][4], bf[8][4];
#pragma unroll
            for (int i = 0; i < 8; i++)
                *(float4*)af[i] = *(const float4*)&sq[(r0 + i) * 68 + d];
#pragma unroll
            for (int j = 0; j < 8; j++)
                *(float4*)bf[j] = *(const float4*)&sk[(c0 + j) * 68 + d];
#pragma unroll
            for (int dd = 0; dd < 4; dd++) {
                u64 bp0 = pk2(bf[0][dd], bf[1][dd]);
                u64 bp1 = pk2(bf[2][dd], bf[3][dd]);
                u64 bp2 = pk2(bf[4][dd], bf[5][dd]);
                u64 bp3 = pk2(bf[6][dd], bf[7][dd]);
#pragma unroll
                for (int i = 0; i < 8; i++) {
                    u64 a = pkd(af[i][dd]);
                    fma2(accp[i][0], a, bp0);
                    fma2(accp[i][1], a, bp1);
                    fma2(accp[i][2], a, bp2);
                    fma2(accp[i][3], a, bp3);
                }
            }
        }
    }
#pragma unroll
    for (int i = 0; i < 8; i++) {
        int r = r0 + i;
        float2 t0 = up2(accp[i][0]), t1 = up2(accp[i][1]);
        float2 t2 = up2(accp[i][2]), t3 = up2(accp[i][3]);
        float vals[8] = { t0.x, t0.y, t1.x, t1.y, t2.x, t2.y, t3.x, t3.y };
#pragma unroll
        for (int j = 0; j < 8; j++)
            if (c0 + j > r) vals[j] = 0.f;
        *(float4*)&ss[r * 132 + c0]     = make_float4(vals[0], vals[1], vals[2], vals[3]);
        *(float4*)&ss[r * 132 + c0 + 4] = make_float4(vals[4], vals[5], vals[6], vals[7]);
    }
    __syncthreads();

    // ---- Phase 2: normalizer z ----
    if (tid < CC) {
        float s = EPSF;
#pragma unroll 4
        for (int c = 0; c < CC; c += 4) {
            float4 t = *(float4*)&ss[tid * 132 + c];
            s += (t.x + t.y) + (t.z + t.w);
        }
#pragma unroll 4
        for (int d = 0; d < DD; d += 4) {
            float4 a = *(float4*)&sq[tid * 68 + d];
            float4 b = *(float4*)&sks[d];
            s = fmaf(a.x, b.x, s); s = fmaf(a.y, b.y, s);
            s = fmaf(a.z, b.z, s); s = fmaf(a.w, b.w, s);
        }
        sz[tid] = s;
    }
    __syncthreads();

    // ---- Phase 3: out = scores @ v + q @ kv_prev (packed), normalized ----
    u64 op[8][2] = {};
    int kmax = r0 + 8;                 // scores row r is zero past col r
#pragma unroll 2
    for (int kk = 0; kk < kmax; kk += 4) {
        float af[8][4], bf[4][4];
#pragma unroll
        for (int i = 0; i < 8; i++)
            *(float4*)af[i] = *(const float4*)&ss[(r0 + i) * 132 + kk];
#pragma unroll
        for (int t = 0; t < 4; t++)
            *(float4*)bf[t] = *(const float4*)&sv[(kk + t) * 68 + m0];
#pragma unroll
        for (int t = 0; t < 4; t++) {
            u64 b0 = pk2(bf[t][0], bf[t][1]);
            u64 b1 = pk2(bf[t][2], bf[t][3]);
#pragma unroll
            for (int i = 0; i < 8; i++) {
                u64 a = pkd(af[i][t]);
                fma2(op[i][0], a, b0);
                fma2(op[i][1], a, b1);
            }
        }
    }
#pragma unroll 2
    for (int d = 0; d < DD; d += 4) {
        float af[8][4], bf[4][4];
#pragma unroll
        for (int i = 0; i < 8; i++)
            *(float4*)af[i] = *(const float4*)&sq[(r0 + i) * 68 + d];
#pragma unroll
        for (int t = 0; t < 4; t++)
            *(float4*)bf[t] = *(const float4*)&skv[(d + t) * 68 + m0];
#pragma unroll
        for (int t = 0; t < 4; t++) {
            u64 b0 = pk2(bf[t][0], bf[t][1]);
            u64 b1 = pk2(bf[t][2], bf[t][3]);
#pragma unroll
            for (int i = 0; i < 8; i++) {
                u64 a = pkd(af[i][t]);
                fma2(op[i][0], a, b0);
                fma2(op[i][1], a, b1);
            }
        }
    }

#pragma unroll
    for (int i = 0; i < 8; i++) {
        int l = g * CC + r0 + i;
        float rz = 1.0f / sz[r0 + i];
        float2 lo = up2(op[i][0]), hi = up2(op[i][1]);
        *(float4*)(out + (((size_t)n * LL + l) * HH + h) * MM + m0) =
            make_float4(lo.x * rz, lo.y * rz, hi.x * rz, hi.y * rz);
    }
}

// ---------------------------------------------------------------------------
extern "C" void kernel_launch(void* const* d_in, const int* in_sizes, int n_in,
                              void* d_out, int out_size)
{
    const float* q = (const float*)d_in[0];
    const float* k = (const float*)d_in[1];
    const float* v = (const float*)d_in[2];
    float* out = (float*)d_out;

    const int SMEM_A = 2 * CC * 68 * (int)sizeof(float);                       // 69632
    const int SMEM_C = (3 * CC * 68 + DD * 68 + DD + CC + CC * 132)
                       * (int)sizeof(float);                                   // 190208

    cudaFuncSetAttribute(chunk_state_kernel,
                         cudaFuncAttributeMaxDynamicSharedMemorySize, SMEM_A);
    cudaFuncSetAttribute(output_kernel,
                         cudaFuncAttributeMaxDynamicSharedMemorySize, SMEM_C);

    chunk_state_kernel<<<NN * GG * HH, 256, SMEM_A>>>(k, v);
    prefix_kernel<<<NN * HH, 256>>>();
    output_kernel<<<NN * GG * HH, 256, SMEM_C>>>(q, k, v, out);
}

// round 4
// speedup vs baseline: 1.6131x; 1.6131x over previous
#include <cuda_runtime.h>
#include <cuda_bf16.h>
#include <math.h>
#include <stdint.h>

#define NN 4
#define LL 4096
#define HH 16
#define DD 64
#define MM 64
#define CC 128
#define GG 32
#define EPSF 1e-6f

typedef unsigned int u32;

// Scratch: kvT[m][d] per (n,g,h) + ksum[d]. Rewritten in place every launch.
static __device__ float g_kv[(size_t)NN * GG * HH * MM * DD];
static __device__ float g_ksum[(size_t)NN * GG * HH * DD];

__device__ __forceinline__ float phi(float x) { return x > 0.f ? x + 1.f : __expf(x); }

__device__ __forceinline__ void bsplit(float x, unsigned short& h, unsigned short& l) {
    __nv_bfloat16 bh = __float2bfloat16(x);
    float fh = __bfloat162float(bh);
    __nv_bfloat16 bl = __float2bfloat16(x - fh);
    h = __bfloat16_as_ushort(bh);
    l = __bfloat16_as_ushort(bl);
}
__device__ __forceinline__ u32 pk(unsigned short a, unsigned short b) {
    return (u32)a | ((u32)b << 16);
}
__device__ __forceinline__ float bf2f(unsigned short u) {
    return __uint_as_float(((u32)u) << 16);
}
// swizzled smem u32 pointer: row-major [row][k], stride SU u32, XOR swizzle
__device__ __forceinline__ u32* sp(u32* base, int row, int cu, int SU) {
    return base + row * SU + (cu ^ ((row >> 2) & 7));
}
// mma.sync m16n8k16 bf16 -> f32 (baseline PTX, works on sm_103 target)
__device__ __forceinline__ void mma16816(float* d, u32 a0, u32 a1, u32 a2, u32 a3,
                                         u32 b0, u32 b1) {
    asm volatile("mma.sync.aligned.m16n8k16.row.col.f32.bf16.bf16.f32 "
                 "{%0,%1,%2,%3},{%4,%5,%6,%7},{%8,%9},{%0,%1,%2,%3};"
                 : "+f"(d[0]), "+f"(d[1]), "+f"(d[2]), "+f"(d[3])
                 : "r"(a0), "r"(a1), "r"(a2), "r"(a3), "r"(b0), "r"(b1));
}

// ---------------------------------------------------------------------------
// Kernel A: chunk state via mma.  kvT[m][d] = sum_c v[c][m] * phi(k)[c][d]
// smem: vT [64 m][c: hi 0..127, lo 128..255], kT same for phi(k). SU=132 u32.
// grid = 2048, block = 256, smem = 67584 B
// ---------------------------------------------------------------------------
#define ASU 132
__global__ void __launch_bounds__(256) chunk_state_kernel(
    const float* __restrict__ k, const float* __restrict__ v)
{
    extern __shared__ u32 smw[];
    u32* sVT = smw;              // 64*132
    u32* sKT = smw + 64 * ASU;   // 64*132

    int tid = threadIdx.x, lane = tid & 31, wid = tid >> 5;
    int bid = blockIdx.x;
    int h = bid % HH;
    int gc = (bid / HH) % GG;
    int n = bid / (HH * GG);
    size_t base = (((size_t)n * LL + (size_t)gc * CC) * HH + h) * DD;

    // transpose-load: k -> phi -> split -> sKT[d][c]; v -> sVT[m][c]
    int e0 = (tid & 15) * 4;           // d/m quad
#pragma unroll
    for (int it = 0; it < 4; it++) {
        int cp = it * 16 + (tid >> 4);  // c pair index 0..63
        int c = cp * 2;
        size_t off0 = base + (size_t)c * (HH * DD) + e0;
        size_t off1 = off0 + (HH * DD);
        float4 ka = *(const float4*)(k + off0);
        float4 kb = *(const float4*)(k + off1);
        float4 va = *(const float4*)(v + off0);
        float4 vb = *(const float4*)(v + off1);
        float fka[4] = { phi(ka.x), phi(ka.y), phi(ka.z), phi(ka.w) };
        float fkb[4] = { phi(kb.x), phi(kb.y), phi(kb.z), phi(kb.w) };
        float fva[4] = { va.x, va.y, va.z, va.w };
        float fvb[4] = { vb.x, vb.y, vb.z, vb.w };
#pragma unroll
        for (int t = 0; t < 4; t++) {
            unsigned short h0, l0, h1, l1;
            bsplit(fka[t], h0, l0); bsplit(fkb[t], h1, l1);
            *sp(sKT, e0 + t, cp, ASU)      = pk(h0, h1);
            *sp(sKT, e0 + t, cp + 64, ASU) = pk(l0, l1);
            bsplit(fva[t], h0, l0); bsplit(fvb[t], h1, l1);
            *sp(sVT, e0 + t, cp, ASU)      = pk(h0, h1);
            *sp(sVT, e0 + t, cp + 64, ASU) = pk(l0, l1);
        }
    }
    __syncthreads();

    // GEMM: M=64 (m), N=64 (d), K=128, 3 passes (hh, lh, hl)
    int grp = lane >> 2, tg = lane & 3;
    int wy = wid >> 1, wx = wid & 1;
    int m0 = wy * 16, nb0 = wx * 32;
    float acc[4][4];
#pragma unroll
    for (int j = 0; j < 4; j++)
#pragma unroll
        for (int t = 0; t < 4; t++) acc[j][t] = 0.f;

    const int aO[3] = { 0, 64, 0 };
    const int bO[3] = { 0, 0, 64 };
#pragma unroll
    for (int p = 0; p < 3; p++) {
#pragma unroll
        for (int ks = 0; ks < 8; ks++) {
            int cu = aO[p] + ks * 8 + tg;
            u32 a0 = *sp(sVT, m0 + grp,     cu, ASU);
            u32 a1 = *sp(sVT, m0 + grp + 8, cu, ASU);
            u32 a2 = *sp(sVT, m0 + grp,     cu + 4, ASU);
            u32 a3 = *sp(sVT, m0 + grp + 8, cu + 4, ASU);
            int cb = bO[p] + ks * 8 + tg;
#pragma unroll
            for (int j = 0; j < 4; j++) {
                int nr = nb0 + j * 8 + grp;
                u32 b0 = *sp(sKT, nr, cb, ASU);
                u32 b1 = *sp(sKT, nr, cb + 4, ASU);
                mma16816(acc[j], a0, a1, a2, a3, b0, b1);
            }
        }
    }

    // write kvT[m][d]
    float* kvout = g_kv + (size_t)bid * (MM * DD);
#pragma unroll
    for (int j = 0; j < 4; j++) {
        int d0c = nb0 + j * 8 + tg * 2;
        *(float2*)(kvout + (size_t)(m0 + grp) * DD + d0c)     = make_float2(acc[j][0], acc[j][1]);
        *(float2*)(kvout + (size_t)(m0 + grp + 8) * DD + d0c) = make_float2(acc[j][2], acc[j][3]);
    }

    // ksum[d] = row-sum of phi(k)T (hi+lo)
    if (tid < DD) {
        float s = 0.f;
#pragma unroll 8
        for (int cu = 0; cu < 64; cu++) {
            u32 uh = *sp(sKT, tid, cu, ASU);
            u32 ul = *sp(sKT, tid, cu + 64, ASU);
            s += bf2f((unsigned short)uh) + bf2f((unsigned short)(uh >> 16))
               + bf2f((unsigned short)ul) + bf2f((unsigned short)(ul >> 16));
        }
        g_ksum[(size_t)bid * DD + tid] = s;
    }
}

// ---------------------------------------------------------------------------
// Kernel B: exclusive prefix over chunks (axis g), in place.
// ---------------------------------------------------------------------------
__global__ void __launch_bounds__(256) prefix_kernel()
{
    int nh = blockIdx.x;
    int n = nh / HH, h = nh % HH;
    for (int pos = threadIdx.x; pos < DD * MM; pos += 256) {
        float run = 0.f;
        for (int g = 0; g < GG; g++) {
            size_t idx = (((size_t)(n * GG + g) * HH) + h) * (DD * MM) + pos;
            float t = g_kv[idx];
            g_kv[idx] = run;
            run += t;
        }
    }
    if (threadIdx.x < DD) {
        float run = 0.f;
        for (int g = 0; g < GG; g++) {
            size_t idx = (((size_t)(n * GG + g) * HH) + h) * DD + threadIdx.x;
            float t = g_ksum[idx];
            g_ksum[idx] = run;
            run += t;
        }
    }
}

// ---------------------------------------------------------------------------
// Kernel C: mma.sync bf16x3.
//   S = tril(phi(q) phi(k)^T); z = rowsum + q.ksum + eps
//   O = (S @ V + Q @ KVprev) / z
// grid = 2048, block = 256 (8 warps), smem = 190208 B
// ---------------------------------------------------------------------------
#define SUQ 68
#define SUS 132
// smem u32 offsets
#define OQ  0
#define OK  (OQ + 128 * SUQ)      // 8704
#define OKV (OK + 128 * SUQ)      // 17408
#define OV  (OKV + 64 * SUQ)      // 21760
#define OS  (OV + 64 * SUS)       // 30208
#define OF  (OS + 128 * SUS)      // 47104
#define SMEM_C ((OF + 256 + 128 + 64) * 4)

__global__ void __launch_bounds__(256) output_kernel(
    const float* __restrict__ q, const float* __restrict__ k,
    const float* __restrict__ v, float* __restrict__ out)
{
    extern __shared__ u32 smw[];
    u32* sQ  = smw + OQ;
    u32* sK  = smw + OK;
    u32* sKV = smw + OKV;
    u32* sV  = smw + OV;
    u32* sS  = smw + OS;
    float* zp  = (float*)(smw + OF);   // [2][128]
    float* sz  = zp + 256;             // [128]
    float* sks = sz + 128;             // [64]

    int tid = threadIdx.x, lane = tid & 31, wid = tid >> 5;
    int bid = blockIdx.x;
    int h = bid % HH;
    int gc = (bid / HH) % GG;
    int n = bid / (HH * GG);
    size_t base = (((size_t)n * LL + (size_t)gc * CC) * HH + h) * DD;

    if (tid < 16)
        *(float4*)(sks + tid * 4) = *(const float4*)(g_ksum + (size_t)bid * DD + tid * 4);

    // --- load Q, K straight: [c row][d k] hi(0..31 u32) / lo(32..63) ---
    for (int i = tid; i < CC * 16; i += 256) {
        int c = i >> 4, dq = (i & 15) * 4;
        size_t off = base + (size_t)c * (HH * DD) + dq;
        float4 q4 = *(const float4*)(q + off);
        float4 k4 = *(const float4*)(k + off);
        float fq[4] = { phi(q4.x), phi(q4.y), phi(q4.z), phi(q4.w) };
        float fk[4] = { phi(k4.x), phi(k4.y), phi(k4.z), phi(k4.w) };
        unsigned short qh[4], ql[4], kh[4], kl[4];
#pragma unroll
        for (int t = 0; t < 4; t++) { bsplit(fq[t], qh[t], ql[t]); bsplit(fk[t], kh[t], kl[t]); }
        int cu = dq >> 1;
        *sp(sQ, c, cu, SUQ)          = pk(qh[0], qh[1]);
        *sp(sQ, c, cu + 1, SUQ)      = pk(qh[2], qh[3]);
        *sp(sQ, c, cu + 32, SUQ)     = pk(ql[0], ql[1]);
        *sp(sQ, c, cu + 33, SUQ)     = pk(ql[2], ql[3]);
        *sp(sK, c, cu, SUQ)          = pk(kh[0], kh[1]);
        *sp(sK, c, cu + 1, SUQ)      = pk(kh[2], kh[3]);
        *sp(sK, c, cu + 32, SUQ)     = pk(kl[0], kl[1]);
        *sp(sK, c, cu + 33, SUQ)     = pk(kl[2], kl[3]);
    }
    // --- transpose-load V: sV[m][c hi 0..63, lo 64..127] ---
    {
        int m0v = (tid & 15) * 4;
#pragma unroll
        for (int it = 0; it < 4; it++) {
            int cp = it * 16 + (tid >> 4);
            int c = cp * 2;
            size_t off0 = base + (size_t)c * (HH * DD) + m0v;
            float4 va = *(const float4*)(v + off0);
            float4 vb = *(const float4*)(v + off0 + HH * DD);
            float fva[4] = { va.x, va.y, va.z, va.w };
            float fvb[4] = { vb.x, vb.y, vb.z, vb.w };
#pragma unroll
            for (int t = 0; t < 4; t++) {
                unsigned short h0, l0, h1, l1;
                bsplit(fva[t], h0, l0); bsplit(fvb[t], h1, l1);
                *sp(sV, m0v + t, cp, SUS)      = pk(h0, h1);
                *sp(sV, m0v + t, cp + 64, SUS) = pk(l0, l1);
            }
        }
    }
    // --- load KVprev (fp32 [m][d]) -> sKV[m][d hi/lo] ---
    {
        const float* kvp = g_kv + (size_t)bid * (MM * DD);
        for (int i = tid; i < DD * 16; i += 256) {
            int m = i >> 4, dq = (i & 15) * 4;
            float4 t4 = *(const float4*)(kvp + (size_t)m * DD + dq);
            float fv[4] = { t4.x, t4.y, t4.z, t4.w };
            unsigned short hh[4], ll[4];
#pragma unroll
            for (int t = 0; t < 4; t++) bsplit(fv[t], hh[t], ll[t]);
            int cu = dq >> 1;
            *sp(sKV, m, cu, SUQ)      = pk(hh[0], hh[1]);
            *sp(sKV, m, cu + 1, SUQ)  = pk(hh[2], hh[3]);
            *sp(sKV, m, cu + 32, SUQ) = pk(ll[0], ll[1]);
            *sp(sKV, m, cu + 33, SUQ) = pk(ll[2], ll[3]);
        }
    }
    __syncthreads();

    int grp = lane >> 2, tg = lane & 3;
    int wy = wid >> 1, wx = wid & 1;
    int m0 = wy * 32;          // 32 rows per warp (2 m-frags)
    int nb0 = wx * 64;         // GEMM1: 64 cols per warp (8 n-frags)

    // ---- GEMM1: S = Q K^T (M=128,N=128,K=64, 3 passes) ----
    float accS[2][8][4];
#pragma unroll
    for (int mf = 0; mf < 2; mf++)
#pragma unroll
        for (int j = 0; j < 8; j++)
#pragma unroll
            for (int t = 0; t < 4; t++) accS[mf][j][t] = 0.f;

    const int aO1[3] = { 0, 32, 0 };
    const int bO1[3] = { 0, 0, 32 };
#pragma unroll
    for (int p = 0; p < 3; p++) {
#pragma unroll
        for (int ks = 0; ks < 4; ks++) {
            int cu = aO1[p] + ks * 8 + tg;
            u32 a[2][4];
#pragma unroll
            for (int mf = 0; mf < 2; mf++) {
                int r = m0 + mf * 16 + grp;
                a[mf][0] = *sp(sQ, r, cu, SUQ);
                a[mf][1] = *sp(sQ, r + 8, cu, SUQ);
                a[mf][2] = *sp(sQ, r, cu + 4, SUQ);
                a[mf][3] = *sp(sQ, r + 8, cu + 4, SUQ);
            }
            int cb = bO1[p] + ks * 8 + tg;
#pragma unroll
            for (int j = 0; j < 8; j++) {
                int nr = nb0 + j * 8 + grp;
                u32 b0 = *sp(sK, nr, cb, SUQ);
                u32 b1 = *sp(sK, nr, cb + 4, SUQ);
                mma16816(accS[0][j], a[0][0], a[0][1], a[0][2], a[0][3], b0, b1);
                mma16816(accS[1][j], a[1][0], a[1][1], a[1][2], a[1][3], b0, b1);
            }
        }
    }

    // ---- mask tril, partial row sums, split S -> smem ----
    float zsm[4] = { 0.f, 0.f, 0.f, 0.f };
#pragma unroll
    for (int mf = 0; mf < 2; mf++) {
        int r0 = m0 + mf * 16 + grp;
#pragma unroll
        for (int j = 0; j < 8; j++) {
            int c0 = nb0 + j * 8 + tg * 2;
            float x0 = (c0     <= r0) ? accS[mf][j][0] : 0.f;
            float x1 = (c0 + 1 <= r0) ? accS[mf][j][1] : 0.f;
            float x2 = (c0     <= r0 + 8) ? accS[mf][j][2] : 0.f;
            float x3 = (c0 + 1 <= r0 + 8) ? accS[mf][j][3] : 0.f;
            zsm[mf * 2]     += x0 + x1;
            zsm[mf * 2 + 1] += x2 + x3;
            unsigned short h0, l0, h1, l1;
            int cu = (nb0 >> 1) + j * 4 + tg;
            bsplit(x0, h0, l0); bsplit(x1, h1, l1);
            *sp(sS, r0, cu, SUS)      = pk(h0, h1);
            *sp(sS, r0, cu + 64, SUS) = pk(l0, l1);
            bsplit(x2, h0, l0); bsplit(x3, h1, l1);
            *sp(sS, r0 + 8, cu, SUS)      = pk(h0, h1);
            *sp(sS, r0 + 8, cu + 64, SUS) = pk(l0, l1);
        }
    }
#pragma unroll
    for (int t = 0; t < 4; t++) {
        zsm[t] += __shfl_xor_sync(0xffffffffu, zsm[t], 1);
        zsm[t] += __shfl_xor_sync(0xffffffffu, zsm[t], 2);
    }
    if (tg == 0) {
        zp[wx * 128 + m0 + grp]      = zsm[0];
        zp[wx * 128 + m0 + grp + 8]  = zsm[1];
        zp[wx * 128 + m0 + grp + 16] = zsm[2];
        zp[wx * 128 + m0 + grp + 24] = zsm[3];
    }
    __syncthreads();

    // ---- z = zp0 + zp1 + q . ksum + eps ----
    if (tid < CC) {
        float s = zp[tid] + zp[128 + tid] + EPSF;
#pragma unroll 8
        for (int cu = 0; cu < 32; cu++) {
            u32 uh = *sp(sQ, tid, cu, SUQ);
            u32 ul = *sp(sQ, tid, cu + 32, SUQ);
            float q0 = bf2f((unsigned short)uh) + bf2f((unsigned short)ul);
            float q1 = bf2f((unsigned short)(uh >> 16)) + bf2f((unsigned short)(ul >> 16));
            s = fmaf(q0, sks[cu * 2], s);
            s = fmaf(q1, sks[cu * 2 + 1], s);
        }
        sz[tid] = s;
    }

    // ---- GEMM2: O = S V + Q KVprev  (M=128, N=64) ----
    float accO[2][4][4];
#pragma unroll
    for (int mf = 0; mf < 2; mf++)
#pragma unroll
        for (int j = 0; j < 4; j++)
#pragma unroll
            for (int t = 0; t < 4; t++) accO[mf][j][t] = 0.f;

    int ob0 = wx * 32;   // GEMM2: 32 cols per warp (4 n-frags)
    // intra: S (K=128, hi 0..63 u32, lo 64..127) x Vt
    const int aO2[3] = { 0, 64, 0 };
    const int bO2[3] = { 0, 0, 64 };
#pragma unroll
    for (int p = 0; p < 3; p++) {
#pragma unroll
        for (int ks = 0; ks < 8; ks++) {
            int cu = aO2[p] + ks * 8 + tg;
            u32 a[2][4];
#pragma unroll
            for (int mf = 0; mf < 2; mf++) {
                int r = m0 + mf * 16 + grp;
                a[mf][0] = *sp(sS, r, cu, SUS);
                a[mf][1] = *sp(sS, r + 8, cu, SUS);
                a[mf][2] = *sp(sS, r, cu + 4, SUS);
                a[mf][3] = *sp(sS, r + 8, cu + 4, SUS);
            }
            int cb = bO2[p] + ks * 8 + tg;
#pragma unroll
            for (int j = 0; j < 4; j++) {
                int nr = ob0 + j * 8 + grp;
                u32 b0 = *sp(sV, nr, cb, SUS);
                u32 b1 = *sp(sV, nr, cb + 4, SUS);
                mma16816(accO[0][j], a[0][0], a[0][1], a[0][2], a[0][3], b0, b1);
                mma16816(accO[1][j], a[1][0], a[1][1], a[1][2], a[1][3], b0, b1);
            }
        }
    }
    // inter: Q (K=64) x KVt
    const int aO3[3] = { 0, 32, 0 };
    const int bO3[3] = { 0, 0, 32 };
#pragma unroll
    for (int p = 0; p < 3; p++) {
#pragma unroll
        for (int ks = 0; ks < 4; ks++) {
            int cu = aO3[p] + ks * 8 + tg;
            u32 a[2][4];
#pragma unroll
            for (int mf = 0; mf < 2; mf++) {
                int r = m0 + mf * 16 + grp;
                a[mf][0] = *sp(sQ, r, cu, SUQ);
                a[mf][1] = *sp(sQ, r + 8, cu, SUQ);
                a[mf][2] = *sp(sQ, r, cu + 4, SUQ);
                a[mf][3] = *sp(sQ, r + 8, cu + 4, SUQ);
            }
            int cb = bO3[p] + ks * 8 + tg;
#pragma unroll
            for (int j = 0; j < 4; j++) {
                int nr = ob0 + j * 8 + grp;
                u32 b0 = *sp(sKV, nr, cb, SUQ);
                u32 b1 = *sp(sKV, nr, cb + 4, SUQ);
                mma16816(accO[0][j], a[0][0], a[0][1], a[0][2], a[0][3], b0, b1);
                mma16816(accO[1][j], a[1][0], a[1][1], a[1][2], a[1][3], b0, b1);
            }
        }
    }
    __syncthreads();   // sz ready for all threads

    // ---- normalize + store ----
#pragma unroll
    for (int mf = 0; mf < 2; mf++) {
        int r = m0 + mf * 16 + grp;
        float rz0 = 1.0f / sz[r];
        float rz1 = 1.0f / sz[r + 8];
        float* op0 = out + (((size_t)n * LL + (size_t)gc * CC + r) * HH + h) * MM;
        float* op1 = op0 + (size_t)8 * HH * MM;
#pragma unroll
        for (int j = 0; j < 4; j++) {
            int col = ob0 + j * 8 + tg * 2;
            *(float2*)(op0 + col) = make_float2(accO[mf][j][0] * rz0, accO[mf][j][1] * rz0);
            *(float2*)(op1 + col) = make_float2(accO[mf][j][2] * rz1, accO[mf][j][3] * rz1);
        }
    }
}

// ---------------------------------------------------------------------------
extern "C" void kernel_launch(void* const* d_in, const int* in_sizes, int n_in,
                              void* d_out, int out_size)
{
    const float* q = (const float*)d_in[0];
    const float* k = (const float*)d_in[1];
    const float* v = (const float*)d_in[2];
    float* out = (float*)d_out;

    const int SMEM_A = 2 * 64 * ASU * (int)sizeof(u32);   // 67584

    cudaFuncSetAttribute(chunk_state_kernel,
                         cudaFuncAttributeMaxDynamicSharedMemorySize, SMEM_A);
    cudaFuncSetAttribute(output_kernel,
                         cudaFuncAttributeMaxDynamicSharedMemorySize, SMEM_C);

    chunk_state_kernel<<<NN * GG * HH, 256, SMEM_A>>>(k, v);
    prefix_kernel<<<NN * HH, 256>>>();
    output_kernel<<<NN * GG * HH, 256, SMEM_C>>>(q, k, v, out);
}

// round 5
// speedup vs baseline: 1.7556x; 1.0883x over previous
#include <cuda_runtime.h>
#include <cuda_bf16.h>
#include <math.h>
#include <stdint.h>

#define NN 4
#define LL 4096
#define HH 16
#define DD 64
#define MM 64
#define CC 128
#define GG 32
#define EPSF 1e-6f

typedef unsigned int u32;

// Scratch: kvT[m][d] per (n,g,h) + ksum[d]. Rewritten in place every launch.
static __device__ float g_kv[(size_t)NN * GG * HH * MM * DD];
static __device__ float g_ksum[(size_t)NN * GG * HH * DD];

__device__ __forceinline__ float phi(float x) { return x > 0.f ? x + 1.f : __expf(x); }

// packed bf16x3 split: h = {bf16(x1), bf16(x0)}, l = residuals. 3 ops/element.
__device__ __forceinline__ void split2(float x0, float x1, u32& h, u32& l) {
    asm("cvt.rn.bf16x2.f32 %0, %1, %2;" : "=r"(h) : "f"(x1), "f"(x0));
    float f0 = __uint_as_float(h << 16);
    float f1 = __uint_as_float(h & 0xFFFF0000u);
    asm("cvt.rn.bf16x2.f32 %0, %1, %2;" : "=r"(l) : "f"(x1 - f1), "f"(x0 - f0));
}
__device__ __forceinline__ float bflo(u32 u) { return __uint_as_float(u << 16); }
__device__ __forceinline__ float bfhi(u32 u) { return __uint_as_float(u & 0xFFFF0000u); }

__device__ __forceinline__ u32 smem_u32(const void* p) {
    u32 a;
    asm("{ .reg .u64 t; cvta.to.shared.u64 t, %1; cvt.u32.u64 %0, t; }" : "=r"(a) : "l"(p));
    return a;
}
__device__ __forceinline__ void ldm4(u32& r0, u32& r1, u32& r2, u32& r3, u32 a) {
    asm volatile("ldmatrix.sync.aligned.m8n8.x4.shared.b16 {%0,%1,%2,%3},[%4];"
                 : "=r"(r0), "=r"(r1), "=r"(r2), "=r"(r3) : "r"(a));
}
__device__ __forceinline__ void ldm2(u32& r0, u32& r1, u32 a) {
    asm volatile("ldmatrix.sync.aligned.m8n8.x2.shared.b16 {%0,%1},[%2];"
                 : "=r"(r0), "=r"(r1) : "r"(a));
}
__device__ __forceinline__ void mma16816(float* d, u32 a0, u32 a1, u32 a2, u32 a3,
                                         u32 b0, u32 b1) {
    asm volatile("mma.sync.aligned.m16n8k16.row.col.f32.bf16.bf16.f32 "
                 "{%0,%1,%2,%3},{%4,%5,%6,%7},{%8,%9},{%0,%1,%2,%3};"
                 : "+f"(d[0]), "+f"(d[1]), "+f"(d[2]), "+f"(d[3])
                 : "r"(a0), "r"(a1), "r"(a2), "r"(a3), "r"(b0), "r"(b1));
}
// swizzled byte offsets: 128B rows / 256B rows, XOR 16B-granule with (row&7)
__device__ __forceinline__ u32 off128(int row, int kb) {
    return (u32)(row * 128) + (u32)(((((kb >> 4) & 7) ^ (row & 7)) << 4) | (kb & 15));
}
__device__ __forceinline__ u32 off256(int row, int kb) {
    return (u32)(row * 256) + (u32)(kb & 128)
         + (u32)(((((kb >> 4) & 7) ^ (row & 7)) << 4) | (kb & 15));
}

// ---------------------------------------------------------------------------
// Kernel A: kvT[m][d] = sum_c v[c][m] * phi(k)[c][d]  via mma bf16x3
// planes: VTH/VTL/KTH/KTL  64 rows x 128 k(c) bf16 (256B rows). smem 64KB.
// ---------------------------------------------------------------------------
__global__ void __launch_bounds__(256, 3) chunk_state_kernel(
    const float* __restrict__ k, const float* __restrict__ v)
{
    extern __shared__ char sm_[];
    const int VTH = 0, VTL = 16384, KTH = 32768, KTL = 49152;
    u32 sb = smem_u32(sm_);

    int tid = threadIdx.x, lane = tid & 31, wid = tid >> 5;
    int bid = blockIdx.x;
    int h = bid % HH;
    int gc = (bid / HH) % GG;
    int n = bid / (HH * GG);
    size_t base = (((size_t)n * LL + (size_t)gc * CC) * HH + h) * DD;

    int e0 = (tid & 15) * 4;
#pragma unroll
    for (int it = 0; it < 4; it++) {
        int cp = it * 16 + (tid >> 4);        // c-pair 0..63
        size_t off0 = base + (size_t)(cp * 2) * (HH * DD) + e0;
        float4 ka = *(const float4*)(k + off0);
        float4 kb = *(const float4*)(k + off0 + HH * DD);
        float4 va = *(const float4*)(v + off0);
        float4 vb = *(const float4*)(v + off0 + HH * DD);
        float fka[4] = { phi(ka.x), phi(ka.y), phi(ka.z), phi(ka.w) };
        float fkb[4] = { phi(kb.x), phi(kb.y), phi(kb.z), phi(kb.w) };
        float fva[4] = { va.x, va.y, va.z, va.w };
        float fvb[4] = { vb.x, vb.y, vb.z, vb.w };
#pragma unroll
        for (int t = 0; t < 4; t++) {
            u32 hh, ll;
            u32 ob = off256(e0 + t, cp * 4);
            split2(fka[t], fkb[t], hh, ll);
            *(u32*)(sm_ + KTH + ob) = hh;
            *(u32*)(sm_ + KTL + ob) = ll;
            split2(fva[t], fvb[t], hh, ll);
            *(u32*)(sm_ + VTH + ob) = hh;
            *(u32*)(sm_ + VTL + ob) = ll;
        }
    }
    __syncthreads();

    int grp = lane >> 2, tg = lane & 3;
    int m0 = (wid >> 1) * 16, n0 = (wid & 1) * 32;
    int rA = m0 + ((lane >> 3) & 1) * 8 + (lane & 7);
    int rB = (lane >> 4) * 8 + (lane & 7);
    int kbA0 = 16 * (lane >> 4);
    int kbB0 = 16 * ((lane >> 3) & 1);

    float acc[4][4] = {};
    const int AP[3] = { VTH, VTL, VTH }, BP[3] = { KTH, KTH, KTL };
#pragma unroll
    for (int p = 0; p < 3; p++) {
#pragma unroll
        for (int ks = 0; ks < 8; ks++) {
            u32 a0, a1, a2, a3;
            ldm4(a0, a1, a2, a3, sb + AP[p] + off256(rA, 32 * ks + kbA0));
#pragma unroll
            for (int jb = 0; jb < 2; jb++) {
                u32 b0, b1, b2, b3;
                ldm4(b0, b1, b2, b3, sb + BP[p] + off256(n0 + jb * 16 + rB, 32 * ks + kbB0));
                mma16816(acc[2 * jb],     a0, a1, a2, a3, b0, b1);
                mma16816(acc[2 * jb + 1], a0, a1, a2, a3, b2, b3);
            }
        }
    }

    float* kvout = g_kv + (size_t)bid * (MM * DD);
#pragma unroll
    for (int j = 0; j < 4; j++) {
        int dc = n0 + (j >> 1) * 16 + (j & 1) * 8 + tg * 2;
        *(float2*)(kvout + (size_t)(m0 + grp) * DD + dc)     = make_float2(acc[j][0], acc[j][1]);
        *(float2*)(kvout + (size_t)(m0 + grp + 8) * DD + dc) = make_float2(acc[j][2], acc[j][3]);
    }

    if (tid < DD) {
        float s = 0.f;
#pragma unroll 8
        for (int cu = 0; cu < 64; cu++) {
            u32 ob = off256(tid, cu * 4);
            u32 uh = *(const u32*)(sm_ + KTH + ob);
            u32 ul = *(const u32*)(sm_ + KTL + ob);
            s += bflo(uh) + bfhi(uh) + bflo(ul) + bfhi(ul);
        }
        g_ksum[(size_t)bid * DD + tid] = s;
    }
}

// ---------------------------------------------------------------------------
// Kernel B: exclusive prefix over chunks (axis g), in place, float4.
// ---------------------------------------------------------------------------
__global__ void __launch_bounds__(256) prefix_kernel()
{
    int nh = blockIdx.x;
    int n = nh / HH, h = nh % HH;
    for (int p4 = threadIdx.x; p4 < (DD * MM) / 4; p4 += 256) {
        float4 run = make_float4(0.f, 0.f, 0.f, 0.f);
        for (int g = 0; g < GG; g++) {
            float4* p = (float4*)(g_kv + (((size_t)(n * GG + g) * HH) + h) * (DD * MM)) + p4;
            float4 t = *p;
            *p = run;
            run.x += t.x; run.y += t.y; run.z += t.z; run.w += t.w;
        }
    }
    if (threadIdx.x < DD / 4) {
        float4 run = make_float4(0.f, 0.f, 0.f, 0.f);
        for (int g = 0; g < GG; g++) {
            float4* p = (float4*)(g_ksum + (((size_t)(n * GG + g) * HH) + h) * DD) + threadIdx.x;
            float4 t = *p;
            *p = run;
            run.x += t.x; run.y += t.y; run.z += t.z; run.w += t.w;
        }
    }
}

// ---------------------------------------------------------------------------
// Kernel C: register-resident S, fused z (N=72 GEMM2), one __syncthreads.
// Warp w owns rows m0 = w*16 .. +15 of the chunk. bf16x3 everywhere.
// planes (bytes): QH 0, QL 16K, KH 32K, KL 48K (128 rows x 128B)
//                 VH 64K, VL 84K (72 rows x 256B: V^T + ones row 64)
//                 WH 100K, WL 109K (72 rows x 128B: KV^T + ksum row 64)
// ---------------------------------------------------------------------------
#define QH 0
#define QL 16384
#define KH 32768
#define KL 49152
#define VH 65536
#define VL 83968
#define WH 102400
#define WL 111616
#define SMEM_C 120832

__global__ void __launch_bounds__(256) output_kernel(
    const float* __restrict__ q, const float* __restrict__ k,
    const float* __restrict__ v, float* __restrict__ out)
{
    extern __shared__ char sm_[];
    u32 sb = smem_u32(sm_);

    int tid = threadIdx.x, lane = tid & 31, wid = tid >> 5;
    int bid = blockIdx.x;
    int h = bid % HH;
    int gc = (bid / HH) % GG;
    int n = bid / (HH * GG);
    size_t base = (((size_t)n * LL + (size_t)gc * CC) * HH + h) * DD;

    // ---- load Q,K rows (phi + split), uint2 stores ----
    for (int i = tid; i < CC * 16; i += 256) {
        int c = i >> 4, dq = (i & 15) << 2;
        size_t off = base + (size_t)c * (HH * DD) + dq;
        float4 q4 = *(const float4*)(q + off);
        float4 k4 = *(const float4*)(k + off);
        u32 h01, l01, h23, l23;
        u32 ob = off128(c, dq * 2);
        split2(phi(q4.x), phi(q4.y), h01, l01);
        split2(phi(q4.z), phi(q4.w), h23, l23);
        *(uint2*)(sm_ + QH + ob) = make_uint2(h01, h23);
        *(uint2*)(sm_ + QL + ob) = make_uint2(l01, l23);
        split2(phi(k4.x), phi(k4.y), h01, l01);
        split2(phi(k4.z), phi(k4.w), h23, l23);
        *(uint2*)(sm_ + KH + ob) = make_uint2(h01, h23);
        *(uint2*)(sm_ + KL + ob) = make_uint2(l01, l23);
    }
    // ---- transpose-load V into V' rows 0..63 ----
    {
        int e0 = (tid & 15) * 4;
#pragma unroll
        for (int it = 0; it < 4; it++) {
            int cp = it * 16 + (tid >> 4);
            size_t off0 = base + (size_t)(cp * 2) * (HH * DD) + e0;
            float4 va = *(const float4*)(v + off0);
            float4 vb = *(const float4*)(v + off0 + HH * DD);
            float fa[4] = { va.x, va.y, va.z, va.w };
            float fb[4] = { vb.x, vb.y, vb.z, vb.w };
#pragma unroll
            for (int t = 0; t < 4; t++) {
                u32 hh, ll;
                split2(fa[t], fb[t], hh, ll);
                u32 ob = off256(e0 + t, cp * 4);
                *(u32*)(sm_ + VH + ob) = hh;
                *(u32*)(sm_ + VL + ob) = ll;
            }
        }
    }
    // ---- KV' rows 0..63 from g_kv ----
    {
        const float* kvp = g_kv + (size_t)bid * (MM * DD);
        for (int i = tid; i < DD * 16; i += 256) {
            int m = i >> 4, dq = (i & 15) << 2;
            float4 t4 = *(const float4*)(kvp + (size_t)m * DD + dq);
            u32 h01, l01, h23, l23;
            split2(t4.x, t4.y, h01, l01);
            split2(t4.z, t4.w, h23, l23);
            u32 ob = off128(m, dq * 2);
            *(uint2*)(sm_ + WH + ob) = make_uint2(h01, h23);
            *(uint2*)(sm_ + WL + ob) = make_uint2(l01, l23);
        }
    }
    // ---- KV' row 64 = ksum_prev ----
    if (tid < 16) {
        float4 t4 = *(const float4*)(g_ksum + (size_t)bid * DD + tid * 4);
        u32 h01, l01, h23, l23;
        split2(t4.x, t4.y, h01, l01);
        split2(t4.z, t4.w, h23, l23);
        u32 ob = off128(64, tid * 8);
        *(uint2*)(sm_ + WH + ob) = make_uint2(h01, h23);
        *(uint2*)(sm_ + WL + ob) = make_uint2(l01, l23);
    }
    // ---- V' rows 64..71 (ones / zero pad), KV' rows 65..71 (zero) ----
    for (int i = tid; i < 512; i += 256) {        // V' rows 64..71, 64 u32/row
        int row = 64 + (i >> 6), cu = i & 63;
        *(u32*)(sm_ + VH + row * 256 + cu * 4) = (row == 64) ? 0x3F803F80u : 0u;
        *(u32*)(sm_ + VL + row * 256 + cu * 4) = 0u;
    }
    if (tid < 224) {                              // KV' rows 65..71, 32 u32/row
        int row = 65 + (tid >> 5), cu = tid & 31;
        *(u32*)(sm_ + WH + row * 128 + cu * 4) = 0u;
        *(u32*)(sm_ + WL + row * 128 + cu * 4) = 0u;
    }
    __syncthreads();

    // ---- warp-local tiles ----
    int grp = lane >> 2, tg = lane & 3;
    int m0 = wid * 16;
    int rA = m0 + ((lane >> 3) & 1) * 8 + (lane & 7);
    int rB = (lane >> 4) * 8 + (lane & 7);
    int kbA0 = 16 * (lane >> 4);
    int kbB0 = 16 * ((lane >> 3) & 1);
    int r9 = 64 + (lane & 7);                     // row for the 9th (z) n-frag

    // ---- GEMM1: S[16 x 128] = phi(q) phi(k)^T, bf16x3 ----
    float accS[16][4] = {};
    const int AP1[3] = { QH, QL, QH }, BP1[3] = { KH, KH, KL };
#pragma unroll
    for (int p = 0; p < 3; p++) {
#pragma unroll
        for (int ks = 0; ks < 4; ks++) {
            u32 a0, a1, a2, a3;
            ldm4(a0, a1, a2, a3, sb + AP1[p] + off128(rA, 32 * ks + kbA0));
#pragma unroll
            for (int jb = 0; jb < 8; jb++) {
                u32 b0, b1, b2, b3;
                ldm4(b0, b1, b2, b3, sb + BP1[p] + off128(jb * 16 + rB, 32 * ks + kbB0));
                mma16816(accS[2 * jb],     a0, a1, a2, a3, b0, b1);
                mma16816(accS[2 * jb + 1], a0, a1, a2, a3, b2, b3);
            }
        }
    }

    // ---- mask tril + in-register split to A-fragments ----
    int r0 = m0 + grp, r1 = r0 + 8;
#pragma unroll
    for (int j = 0; j < 16; j++) {
        int c0 = j * 8 + tg * 2;
        if (c0 > r0)     accS[j][0] = 0.f;
        if (c0 + 1 > r0) accS[j][1] = 0.f;
        if (c0 > r1)     accS[j][2] = 0.f;
        if (c0 + 1 > r1) accS[j][3] = 0.f;
    }
    u32 Sh[8][4], Sl[8][4];
#pragma unroll
    for (int ks = 0; ks < 8; ks++) {
        split2(accS[2 * ks][0],     accS[2 * ks][1],     Sh[ks][0], Sl[ks][0]);
        split2(accS[2 * ks][2],     accS[2 * ks][3],     Sh[ks][1], Sl[ks][1]);
        split2(accS[2 * ks + 1][0], accS[2 * ks + 1][1], Sh[ks][2], Sl[ks][2]);
        split2(accS[2 * ks + 1][2], accS[2 * ks + 1][3], Sh[ks][3], Sl[ks][3]);
    }

    // ---- GEMM2: O' [16 x 72] = S V'^T + Q KV'^T  (col 64 = z) ----
    float accO[9][4] = {};
    const int BP2[3] = { VH, VH, VL };
#pragma unroll
    for (int p = 0; p < 3; p++) {
#pragma unroll
        for (int ks = 0; ks < 8; ks++) {
            u32 a0 = (p == 1) ? Sl[ks][0] : Sh[ks][0];
            u32 a1 = (p == 1) ? Sl[ks][1] : Sh[ks][1];
            u32 a2 = (p == 1) ? Sl[ks][2] : Sh[ks][2];
            u32 a3 = (p == 1) ? Sl[ks][3] : Sh[ks][3];
            int kb = 32 * ks + kbB0;
#pragma unroll
            for (int jb = 0; jb < 4; jb++) {
                u32 b0, b1, b2, b3;
                ldm4(b0, b1, b2, b3, sb + BP2[p] + off256(jb * 16 + rB, kb));
                mma16816(accO[2 * jb],     a0, a1, a2, a3, b0, b1);
                mma16816(accO[2 * jb + 1], a0, a1, a2, a3, b2, b3);
            }
            u32 b0, b1;
            ldm2(b0, b1, sb + BP2[p] + off256(r9, kb));
            mma16816(accO[8], a0, a1, a2, a3, b0, b1);
        }
    }
    const int AP3[3] = { QH, QL, QH }, BP3[3] = { WH, WH, WL };
#pragma unroll
    for (int p = 0; p < 3; p++) {
#pragma unroll
        for (int ks = 0; ks < 4; ks++) {
            u32 a0, a1, a2, a3;
            ldm4(a0, a1, a2, a3, sb + AP3[p] + off128(rA, 32 * ks + kbA0));
            int kb = 32 * ks + kbB0;
#pragma unroll
            for (int jb = 0; jb < 4; jb++) {
                u32 b0, b1, b2, b3;
                ldm4(b0, b1, b2, b3, sb + BP3[p] + off128(jb * 16 + rB, kb));
                mma16816(accO[2 * jb],     a0, a1, a2, a3, b0, b1);
                mma16816(accO[2 * jb + 1], a0, a1, a2, a3, b2, b3);
            }
            u32 b0, b1;
            ldm2(b0, b1, sb + BP3[p] + off128(r9, kb));
            mma16816(accO[8], a0, a1, a2, a3, b0, b1);
        }
    }

    // ---- normalize + store (z = col 64 of O') ----
    float zr0 = __shfl_sync(0xffffffffu, accO[8][0], lane & 28);
    float zr1 = __shfl_sync(0xffffffffu, accO[8][2], lane & 28);
    float rz0 = 1.0f / (zr0 + EPSF);
    float rz1 = 1.0f / (zr1 + EPSF);
    float* op0 = out + (((size_t)n * LL + (size_t)gc * CC + r0) * HH + h) * MM;
    float* op1 = op0 + (size_t)8 * HH * MM;
#pragma unroll
    for (int j = 0; j < 8; j++) {
        int c0 = j * 8 + tg * 2;
        *(float2*)(op0 + c0) = make_float2(accO[j][0] * rz0, accO[j][1] * rz0);
        *(float2*)(op1 + c0) = make_float2(accO[j][2] * rz1, accO[j][3] * rz1);
    }
}

// ---------------------------------------------------------------------------
extern "C" void kernel_launch(void* const* d_in, const int* in_sizes, int n_in,
                              void* d_out, int out_size)
{
    const float* q = (const float*)d_in[0];
    const float* k = (const float*)d_in[1];
    const float* v = (const float*)d_in[2];
    float* out = (float*)d_out;

    const int SMEM_A = 65536;

    cudaFuncSetAttribute(chunk_state_kernel,
                         cudaFuncAttributeMaxDynamicSharedMemorySize, SMEM_A);
    cudaFuncSetAttribute(output_kernel,
                         cudaFuncAttributeMaxDynamicSharedMemorySize, SMEM_C);

    chunk_state_kernel<<<NN * GG * HH, 256, SMEM_A>>>(k, v);
    prefix_kernel<<<NN * HH, 256>>>();
    output_kernel<<<NN * GG * HH, 256, SMEM_C>>>(q, k, v, out);
}

// round 6
// speedup vs baseline: 1.8809x; 1.0714x over previous
#include <cuda_runtime.h>
#include <cuda_bf16.h>
#include <math.h>
#include <stdint.h>

#define NN 4
#define LL 4096
#define HH 16
#define DD 64
#define MM 64
#define CC 128
#define GG 32
#define EPSF 1e-6f

typedef unsigned int u32;

static __device__ float g_kv[(size_t)NN * GG * HH * MM * DD];
static __device__ float g_ksum[(size_t)NN * GG * HH * DD];

__device__ __forceinline__ float phi(float x) { return x > 0.f ? x + 1.f : __expf(x); }

__device__ __forceinline__ void split2(float x0, float x1, u32& h, u32& l) {
    asm("cvt.rn.bf16x2.f32 %0, %1, %2;" : "=r"(h) : "f"(x1), "f"(x0));
    float f0 = __uint_as_float(h << 16);
    float f1 = __uint_as_float(h & 0xFFFF0000u);
    asm("cvt.rn.bf16x2.f32 %0, %1, %2;" : "=r"(l) : "f"(x1 - f1), "f"(x0 - f0));
}
__device__ __forceinline__ float bflo(u32 u) { return __uint_as_float(u << 16); }
__device__ __forceinline__ float bfhi(u32 u) { return __uint_as_float(u & 0xFFFF0000u); }

__device__ __forceinline__ u32 smem_u32(const void* p) {
    u32 a;
    asm("{ .reg .u64 t; cvta.to.shared.u64 t, %1; cvt.u32.u64 %0, t; }" : "=r"(a) : "l"(p));
    return a;
}
__device__ __forceinline__ void ldm4(u32& r0, u32& r1, u32& r2, u32& r3, u32 a) {
    asm volatile("ldmatrix.sync.aligned.m8n8.x4.shared.b16 {%0,%1,%2,%3},[%4];"
                 : "=r"(r0), "=r"(r1), "=r"(r2), "=r"(r3) : "r"(a));
}
__device__ __forceinline__ void ldm2(u32& r0, u32& r1, u32 a) {
    asm volatile("ldmatrix.sync.aligned.m8n8.x2.shared.b16 {%0,%1},[%2];"
                 : "=r"(r0), "=r"(r1) : "r"(a));
}
__device__ __forceinline__ void mma16816(float* d, u32 a0, u32 a1, u32 a2, u32 a3,
                                         u32 b0, u32 b1) {
    asm volatile("mma.sync.aligned.m16n8k16.row.col.f32.bf16.bf16.f32 "
                 "{%0,%1,%2,%3},{%4,%5,%6,%7},{%8,%9},{%0,%1,%2,%3};"
                 : "+f"(d[0]), "+f"(d[1]), "+f"(d[2]), "+f"(d[3])
                 : "r"(a0), "r"(a1), "r"(a2), "r"(a3), "r"(b0), "r"(b1));
}
__device__ __forceinline__ u32 off128(int row, int kb) {
    return (u32)(row * 128) + (u32)(((((kb >> 4) & 7) ^ (row & 7)) << 4) | (kb & 15));
}
__device__ __forceinline__ u32 off256(int row, int kb) {
    return (u32)(row * 256) + (u32)(kb & 128)
         + (u32)(((((kb >> 4) & 7) ^ (row & 7)) << 4) | (kb & 15));
}

// ---------------------------------------------------------------------------
// Kernel A: kvT[m][d] = sum_c v[c][m] * phi(k)[c][d]  (mma bf16x3, fused passes)
// ---------------------------------------------------------------------------
__global__ void __launch_bounds__(256, 3) chunk_state_kernel(
    const float* __restrict__ k, const float* __restrict__ v)
{
    extern __shared__ char sm_[];
    const int VTH = 0, VTL = 16384, KTH = 32768, KTL = 49152;
    u32 sb = smem_u32(sm_);

    int tid = threadIdx.x, lane = tid & 31, wid = tid >> 5;
    int bid = blockIdx.x;
    int h = bid % HH;
    int gc = (bid / HH) % GG;
    int n = bid / (HH * GG);
    size_t base = (((size_t)n * LL + (size_t)gc * CC) * HH + h) * DD;

    int e0 = (tid & 15) * 4;
#pragma unroll
    for (int it = 0; it < 4; it++) {
        int cp = it * 16 + (tid >> 4);
        size_t off0 = base + (size_t)(cp * 2) * (HH * DD) + e0;
        float4 ka = *(const float4*)(k + off0);
        float4 kb = *(const float4*)(k + off0 + HH * DD);
        float4 va = *(const float4*)(v + off0);
        float4 vb = *(const float4*)(v + off0 + HH * DD);
        float fka[4] = { phi(ka.x), phi(ka.y), phi(ka.z), phi(ka.w) };
        float fkb[4] = { phi(kb.x), phi(kb.y), phi(kb.z), phi(kb.w) };
        float fva[4] = { va.x, va.y, va.z, va.w };
        float fvb[4] = { vb.x, vb.y, vb.z, vb.w };
#pragma unroll
        for (int t = 0; t < 4; t++) {
            u32 hh, ll;
            u32 ob = off256(e0 + t, cp * 4);
            split2(fka[t], fkb[t], hh, ll);
            *(u32*)(sm_ + KTH + ob) = hh;
            *(u32*)(sm_ + KTL + ob) = ll;
            split2(fva[t], fvb[t], hh, ll);
            *(u32*)(sm_ + VTH + ob) = hh;
            *(u32*)(sm_ + VTL + ob) = ll;
        }
    }
    __syncthreads();

    int grp = lane >> 2, tg = lane & 3;
    int m0 = (wid >> 1) * 16, n0 = (wid & 1) * 32;
    int rA = m0 + ((lane >> 3) & 1) * 8 + (lane & 7);
    int rB = (lane >> 4) * 8 + (lane & 7);
    int kbA0 = 16 * (lane >> 4);
    int kbB0 = 16 * ((lane >> 3) & 1);

    float acc[4][4] = {};
#pragma unroll
    for (int ks = 0; ks < 8; ks++) {
        u32 ah0, ah1, ah2, ah3, al0, al1, al2, al3;
        ldm4(ah0, ah1, ah2, ah3, sb + VTH + off256(rA, 32 * ks + kbA0));
        ldm4(al0, al1, al2, al3, sb + VTL + off256(rA, 32 * ks + kbA0));
#pragma unroll
        for (int jb = 0; jb < 2; jb++) {
            u32 b0, b1, b2, b3;
            u32 obB = off256(n0 + jb * 16 + rB, 32 * ks + kbB0);
            ldm4(b0, b1, b2, b3, sb + KTH + obB);
            mma16816(acc[2 * jb],     ah0, ah1, ah2, ah3, b0, b1);
            mma16816(acc[2 * jb + 1], ah0, ah1, ah2, ah3, b2, b3);
            mma16816(acc[2 * jb],     al0, al1, al2, al3, b0, b1);
            mma16816(acc[2 * jb + 1], al0, al1, al2, al3, b2, b3);
            ldm4(b0, b1, b2, b3, sb + KTL + obB);
            mma16816(acc[2 * jb],     ah0, ah1, ah2, ah3, b0, b1);
            mma16816(acc[2 * jb + 1], ah0, ah1, ah2, ah3, b2, b3);
        }
    }

    float* kvout = g_kv + (size_t)bid * (MM * DD);
#pragma unroll
    for (int j = 0; j < 4; j++) {
        int dc = n0 + (j >> 1) * 16 + (j & 1) * 8 + tg * 2;
        *(float2*)(kvout + (size_t)(m0 + grp) * DD + dc)     = make_float2(acc[j][0], acc[j][1]);
        *(float2*)(kvout + (size_t)(m0 + grp + 8) * DD + dc) = make_float2(acc[j][2], acc[j][3]);
    }

    if (tid < DD) {
        float s = 0.f;
#pragma unroll 8
        for (int j = 0; j < 64; j++) {
            int cu = (j + (tid >> 3) * 8) & 63;   // staggered: conflict-free
            u32 ob = off256(tid, cu * 4);
            u32 uh = *(const u32*)(sm_ + KTH + ob);
            u32 ul = *(const u32*)(sm_ + KTL + ob);
            s += bflo(uh) + bfhi(uh) + bflo(ul) + bfhi(ul);
        }
        g_ksum[(size_t)bid * DD + tid] = s;
    }
}

// ---------------------------------------------------------------------------
// Kernel B: exclusive prefix over chunks, grid=256, 1 float4 chain/thread
// ---------------------------------------------------------------------------
__global__ void __launch_bounds__(256) prefix_kernel()
{
    int nh = blockIdx.x >> 2, qtr = blockIdx.x & 3;
    int n = nh / HH, h = nh % HH;
    int p4 = qtr * 256 + threadIdx.x;    // 0..1023
    float4 run = make_float4(0.f, 0.f, 0.f, 0.f);
    for (int g = 0; g < GG; g++) {
        float4* p = (float4*)(g_kv + (((size_t)(n * GG + g) * HH) + h) * (DD * MM)) + p4;
        float4 t = *p;
        *p = run;
        run.x += t.x; run.y += t.y; run.z += t.z; run.w += t.w;
    }
    if (qtr == 0 && threadIdx.x < DD / 4) {
        float4 rs = make_float4(0.f, 0.f, 0.f, 0.f);
        for (int g = 0; g < GG; g++) {
            float4* p = (float4*)(g_ksum + (((size_t)(n * GG + g) * HH) + h) * DD) + threadIdx.x;
            float4 t = *p;
            *p = rs;
            rs.x += t.x; rs.y += t.y; rs.z += t.z; rs.w += t.w;
        }
    }
}

// ---------------------------------------------------------------------------
// Kernel C: register S, fused z, triangle-skipped, SMSP-balanced warp perm.
// ---------------------------------------------------------------------------
#define QH 0
#define QL 16384
#define KH 32768
#define KL 49152
#define VH 65536
#define VL 83968
#define WH 102400
#define WL 111616
#define SMEM_C 120832

__global__ void __launch_bounds__(256) output_kernel(
    const float* __restrict__ q, const float* __restrict__ k,
    const float* __restrict__ v, float* __restrict__ out)
{
    extern __shared__ char sm_[];
    u32 sb = smem_u32(sm_);

    int tid = threadIdx.x, lane = tid & 31, wid = tid >> 5;
    int bid = blockIdx.x;
    int h = bid % HH;
    int gc = (bid / HH) % GG;
    int n = bid / (HH * GG);
    size_t base = (((size_t)n * LL + (size_t)gc * CC) * HH + h) * DD;

    // ---- loads (same as R5) ----
    for (int i = tid; i < CC * 16; i += 256) {
        int c = i >> 4, dq = (i & 15) << 2;
        size_t off = base + (size_t)c * (HH * DD) + dq;
        float4 q4 = *(const float4*)(q + off);
        float4 k4 = *(const float4*)(k + off);
        u32 h01, l01, h23, l23;
        u32 ob = off128(c, dq * 2);
        split2(phi(q4.x), phi(q4.y), h01, l01);
        split2(phi(q4.z), phi(q4.w), h23, l23);
        *(uint2*)(sm_ + QH + ob) = make_uint2(h01, h23);
        *(uint2*)(sm_ + QL + ob) = make_uint2(l01, l23);
        split2(phi(k4.x), phi(k4.y), h01, l01);
        split2(phi(k4.z), phi(k4.w), h23, l23);
        *(uint2*)(sm_ + KH + ob) = make_uint2(h01, h23);
        *(uint2*)(sm_ + KL + ob) = make_uint2(l01, l23);
    }
    {
        int e0 = (tid & 15) * 4;
#pragma unroll
        for (int it = 0; it < 4; it++) {
            int cp = it * 16 + (tid >> 4);
            size_t off0 = base + (size_t)(cp * 2) * (HH * DD) + e0;
            float4 va = *(const float4*)(v + off0);
            float4 vb = *(const float4*)(v + off0 + HH * DD);
            float fa[4] = { va.x, va.y, va.z, va.w };
            float fb[4] = { vb.x, vb.y, vb.z, vb.w };
#pragma unroll
            for (int t = 0; t < 4; t++) {
                u32 hh, ll;
                split2(fa[t], fb[t], hh, ll);
                u32 ob = off256(e0 + t, cp * 4);
                *(u32*)(sm_ + VH + ob) = hh;
                *(u32*)(sm_ + VL + ob) = ll;
            }
        }
    }
    {
        const float* kvp = g_kv + (size_t)bid * (MM * DD);
        for (int i = tid; i < DD * 16; i += 256) {
            int m = i >> 4, dq = (i & 15) << 2;
            float4 t4 = *(const float4*)(kvp + (size_t)m * DD + dq);
            u32 h01, l01, h23, l23;
            split2(t4.x, t4.y, h01, l01);
            split2(t4.z, t4.w, h23, l23);
            u32 ob = off128(m, dq * 2);
            *(uint2*)(sm_ + WH + ob) = make_uint2(h01, h23);
            *(uint2*)(sm_ + WL + ob) = make_uint2(l01, l23);
        }
    }
    if (tid < 16) {
        float4 t4 = *(const float4*)(g_ksum + (size_t)bid * DD + tid * 4);
        u32 h01, l01, h23, l23;
        split2(t4.x, t4.y, h01, l01);
        split2(t4.z, t4.w, h23, l23);
        u32 ob = off128(64, tid * 8);
        *(uint2*)(sm_ + WH + ob) = make_uint2(h01, h23);
        *(uint2*)(sm_ + WL + ob) = make_uint2(l01, l23);
    }
    for (int i = tid; i < 512; i += 256) {
        int row = 64 + (i >> 6), cu = i & 63;
        *(u32*)(sm_ + VH + row * 256 + cu * 4) = (row == 64) ? 0x3F803F80u : 0u;
        *(u32*)(sm_ + VL + row * 256 + cu * 4) = 0u;
    }
    if (tid < 224) {
        int row = 65 + (tid >> 5), cu = tid & 31;
        *(u32*)(sm_ + WH + row * 128 + cu * 4) = 0u;
        *(u32*)(sm_ + WL + row * 128 + cu * 4) = 0u;
    }
    __syncthreads();

    // ---- SMSP-balanced row-block permutation ----
    const int perm[8] = { 0, 7, 1, 6, 2, 5, 3, 4 };
    int wb = perm[wid];
    int m0 = wb * 16;
    int grp = lane >> 2, tg = lane & 3;
    int rA = m0 + ((lane >> 3) & 1) * 8 + (lane & 7);
    int rB = (lane >> 4) * 8 + (lane & 7);
    int kbA0 = 16 * (lane >> 4);
    int kbB0 = 16 * ((lane >> 3) & 1);
    int r9 = 64 + (lane & 7);

    // ---- GEMM1: S rows m0..m0+15, cols 0..16*wb+15 only (tril) ----
    float accS[16][4] = {};
    u32 qhA[4][4], qlA[4][4];                  // Q fragments kept for inter GEMM
#pragma unroll
    for (int ks = 0; ks < 4; ks++) {
        ldm4(qhA[ks][0], qhA[ks][1], qhA[ks][2], qhA[ks][3],
             sb + QH + off128(rA, 32 * ks + kbA0));
        ldm4(qlA[ks][0], qlA[ks][1], qlA[ks][2], qlA[ks][3],
             sb + QL + off128(rA, 32 * ks + kbA0));
#pragma unroll
        for (int jb = 0; jb < 8; jb++) {
            if (jb <= wb) {
                u32 b0, b1, b2, b3;
                u32 obB = off128(jb * 16 + rB, 32 * ks + kbB0);
                ldm4(b0, b1, b2, b3, sb + KH + obB);
                mma16816(accS[2 * jb],     qhA[ks][0], qhA[ks][1], qhA[ks][2], qhA[ks][3], b0, b1);
                mma16816(accS[2 * jb + 1], qhA[ks][0], qhA[ks][1], qhA[ks][2], qhA[ks][3], b2, b3);
                mma16816(accS[2 * jb],     qlA[ks][0], qlA[ks][1], qlA[ks][2], qlA[ks][3], b0, b1);
                mma16816(accS[2 * jb + 1], qlA[ks][0], qlA[ks][1], qlA[ks][2], qlA[ks][3], b2, b3);
                ldm4(b0, b1, b2, b3, sb + KL + obB);
                mma16816(accS[2 * jb],     qhA[ks][0], qhA[ks][1], qhA[ks][2], qhA[ks][3], b0, b1);
                mma16816(accS[2 * jb + 1], qhA[ks][0], qhA[ks][1], qhA[ks][2], qhA[ks][3], b2, b3);
            }
        }
    }

    // ---- mask tril + in-register split ----
    int r0 = m0 + grp, r1 = r0 + 8;
#pragma unroll
    for (int j = 0; j < 16; j++) {
        int c0 = j * 8 + tg * 2;
        if (c0 > r0)     accS[j][0] = 0.f;
        if (c0 + 1 > r0) accS[j][1] = 0.f;
        if (c0 > r1)     accS[j][2] = 0.f;
        if (c0 + 1 > r1) accS[j][3] = 0.f;
    }
    u32 Sh[8][4], Sl[8][4];
#pragma unroll
    for (int ks = 0; ks < 8; ks++) {
        split2(accS[2 * ks][0],     accS[2 * ks][1],     Sh[ks][0], Sl[ks][0]);
        split2(accS[2 * ks][2],     accS[2 * ks][3],     Sh[ks][1], Sl[ks][1]);
        split2(accS[2 * ks + 1][0], accS[2 * ks + 1][1], Sh[ks][2], Sl[ks][2]);
        split2(accS[2 * ks + 1][2], accS[2 * ks + 1][3], Sh[ks][3], Sl[ks][3]);
    }

    // ---- GEMM2 intra: only ks <= wb (S cols zero beyond) ----
    float accO[9][4] = {};
#pragma unroll
    for (int ks = 0; ks < 8; ks++) {
        if (ks <= wb) {
            int kb = 32 * ks + kbB0;
#pragma unroll
            for (int jb = 0; jb < 4; jb++) {
                u32 b0, b1, b2, b3;
                u32 obB = off256(jb * 16 + rB, kb);
                ldm4(b0, b1, b2, b3, sb + VH + obB);
                mma16816(accO[2 * jb],     Sh[ks][0], Sh[ks][1], Sh[ks][2], Sh[ks][3], b0, b1);
                mma16816(accO[2 * jb + 1], Sh[ks][0], Sh[ks][1], Sh[ks][2], Sh[ks][3], b2, b3);
                mma16816(accO[2 * jb],     Sl[ks][0], Sl[ks][1], Sl[ks][2], Sl[ks][3], b0, b1);
                mma16816(accO[2 * jb + 1], Sl[ks][0], Sl[ks][1], Sl[ks][2], Sl[ks][3], b2, b3);
                ldm4(b0, b1, b2, b3, sb + VL + obB);
                mma16816(accO[2 * jb],     Sh[ks][0], Sh[ks][1], Sh[ks][2], Sh[ks][3], b0, b1);
                mma16816(accO[2 * jb + 1], Sh[ks][0], Sh[ks][1], Sh[ks][2], Sh[ks][3], b2, b3);
            }
            u32 b0, b1;
            ldm2(b0, b1, sb + VH + off256(r9, kb));
            mma16816(accO[8], Sh[ks][0], Sh[ks][1], Sh[ks][2], Sh[ks][3], b0, b1);
            mma16816(accO[8], Sl[ks][0], Sl[ks][1], Sl[ks][2], Sl[ks][3], b0, b1);
            ldm2(b0, b1, sb + VL + off256(r9, kb));
            mma16816(accO[8], Sh[ks][0], Sh[ks][1], Sh[ks][2], Sh[ks][3], b0, b1);
        }
    }
    // ---- GEMM2 inter: Q (regs) x KV'  (full K=64) ----
#pragma unroll
    for (int ks = 0; ks < 4; ks++) {
        int kb = 32 * ks + kbB0;
#pragma unroll
        for (int jb = 0; jb < 4; jb++) {
            u32 b0, b1, b2, b3;
            u32 obB = off128(jb * 16 + rB, kb);
            ldm4(b0, b1, b2, b3, sb + WH + obB);
            mma16816(accO[2 * jb],     qhA[ks][0], qhA[ks][1], qhA[ks][2], qhA[ks][3], b0, b1);
            mma16816(accO[2 * jb + 1], qhA[ks][0], qhA[ks][1], qhA[ks][2], qhA[ks][3], b2, b3);
            mma16816(accO[2 * jb],     qlA[ks][0], qlA[ks][1], qlA[ks][2], qlA[ks][3], b0, b1);
            mma16816(accO[2 * jb + 1], qlA[ks][0], qlA[ks][1], qlA[ks][2], qlA[ks][3], b2, b3);
            ldm4(b0, b1, b2, b3, sb + WL + obB);
            mma16816(accO[2 * jb],     qhA[ks][0], qhA[ks][1], qhA[ks][2], qhA[ks][3], b0, b1);
            mma16816(accO[2 * jb + 1], qhA[ks][0], qhA[ks][1], qhA[ks][2], qhA[ks][3], b2, b3);
        }
        u32 b0, b1;
        ldm2(b0, b1, sb + WH + off128(r9, kb));
        mma16816(accO[8], qhA[ks][0], qhA[ks][1], qhA[ks][2], qhA[ks][3], b0, b1);
        mma16816(accO[8], qlA[ks][0], qlA[ks][1], qlA[ks][2], qlA[ks][3], b0, b1);
        ldm2(b0, b1, sb + WL + off128(r9, kb));
        mma16816(accO[8], qhA[ks][0], qhA[ks][1], qhA[ks][2], qhA[ks][3], b0, b1);
    }

    // ---- normalize + store ----
    float zr0 = __shfl_sync(0xffffffffu, accO[8][0], lane & 28);
    float zr1 = __shfl_sync(0xffffffffu, accO[8][2], lane & 28);
    float rz0 = 1.0f / (zr0 + EPSF);
    float rz1 = 1.0f / (zr1 + EPSF);
    float* op0 = out + (((size_t)n * LL + (size_t)gc * CC + r0) * HH + h) * MM;
    float* op1 = op0 + (size_t)8 * HH * MM;
#pragma unroll
    for (int j = 0; j < 8; j++) {
        int c0 = j * 8 + tg * 2;
        *(float2*)(op0 + c0) = make_float2(accO[j][0] * rz0, accO[j][1] * rz0);
        *(float2*)(op1 + c0) = make_float2(accO[j][2] * rz1, accO[j][3] * rz1);
    }
}

// ---------------------------------------------------------------------------
extern "C" void kernel_launch(void* const* d_in, const int* in_sizes, int n_in,
                              void* d_out, int out_size)
{
    const float* q = (const float*)d_in[0];
    const float* k = (const float*)d_in[1];
    const float* v = (const float*)d_in[2];
    float* out = (float*)d_out;

    const int SMEM_A = 65536;

    cudaFuncSetAttribute(chunk_state_kernel,
                         cudaFuncAttributeMaxDynamicSharedMemorySize, SMEM_A);
    cudaFuncSetAttribute(output_kernel,
                         cudaFuncAttributeMaxDynamicSharedMemorySize, SMEM_C);

    chunk_state_kernel<<<NN * GG * HH, 256, SMEM_A>>>(k, v);
    prefix_kernel<<<NN * HH * 4, 256>>>();
    output_kernel<<<NN * GG * HH, 256, SMEM_C>>>(q, k, v, out);
}